// round 10
// baseline (speedup 1.0000x reference)
#include <cuda_runtime.h>
#include <cuda_bf16.h>
#include <cstdint>

#define BATCH 2048
#define INF   512
#define OUTF  512
#define NAG   64

#define MT   128            /* block M (out features), 4 warps x 32 */
#define NT   32             /* block N (batch rows) */
#define TK   32             /* k chunk */
#define NCH  (INF / TK)     /* 16 */

/* smem per stage: Whi[128x32 bf16, row stride 80B] + Wlo + Xhi[32x32] + Xlo */
#define WROW_B   80
#define ST_WHI   0
#define ST_WLO   10240
#define ST_XHI   20480
#define ST_XLO   23040
#define ST_SIZE  25600
#define SM_TOT   (2 * ST_SIZE)   /* 51200 bytes */

__device__ int g_bucket[BATCH];
__device__ int g_offsets[NAG + 1];
/* X pre-converted: per (chunk, row): 32 u32 = [q0: 4 hi, 4 lo][q1: ...] 128B */
__device__ uint32_t g_xs[NCH][BATCH][32];

__device__ __forceinline__ uint32_t smem_u32(const void* p) {
    uint32_t a;
    asm("{ .reg .u64 t; cvta.to.shared.u64 t, %1; cvt.u32.u64 %0, t; }" : "=r"(a) : "l"(p));
    return a;
}

#define LDSM_X4(r0, r1, r2, r3, addr) \
    asm volatile("ldmatrix.sync.aligned.m8n8.x4.shared.b16 {%0,%1,%2,%3}, [%4];" \
        : "=r"(r0), "=r"(r1), "=r"(r2), "=r"(r3) : "r"(addr))

#define CP_ASYNC16(dst, src) \
    asm volatile("cp.async.cg.shared.global [%0], [%1], 16;" :: "r"(dst), "l"(src) : "memory")
#define CP_WAIT_ALL() asm volatile("cp.async.wait_all;" ::: "memory")

/* split 2 floats into packed bf16 hi-word and residual lo-word (lo 16 bits = f0) */
__device__ __forceinline__ void split2(float f0, float f1, uint32_t& h, uint32_t& l) {
    asm("cvt.rn.bf16x2.f32 %0, %1, %2;" : "=r"(h) : "f"(f1), "f"(f0));
    float r0 = f0 - __uint_as_float(h << 16);
    float r1 = f1 - __uint_as_float(h & 0xFFFF0000u);
    asm("cvt.rn.bf16x2.f32 %0, %1, %2;" : "=r"(l) : "f"(r1), "f"(r0));
}

__device__ __forceinline__ void mma_bf16(float* c, const uint32_t* a, const uint32_t* b) {
    asm volatile(
        "mma.sync.aligned.m16n8k16.row.col.f32.bf16.bf16.f32 "
        "{%0,%1,%2,%3}, {%4,%5,%6,%7}, {%8,%9}, {%0,%1,%2,%3};"
        : "+f"(c[0]), "+f"(c[1]), "+f"(c[2]), "+f"(c[3])
        : "r"(a[0]), "r"(a[1]), "r"(a[2]), "r"(a[3]), "r"(b[0]), "r"(b[1]));
}

/* ------- kernel 1: block 0 = counting sort; blocks 1.. = X convert ------- */
__global__ __launch_bounds__(256) void prep_kernel(
    const int* __restrict__ which, const float* __restrict__ x)
{
    const int t = threadIdx.x;
    if (blockIdx.x == 0) {
        __shared__ int cnt[NAG];
        __shared__ int run[NAG];
        if (t < NAG) cnt[t] = 0;
        __syncthreads();
        for (int i = t; i < BATCH; i += 256) atomicAdd(&cnt[which[i]], 1);
        __syncthreads();
        if (t == 0) {
            int s = 0;
            for (int a = 0; a < NAG; a++) { run[a] = s; g_offsets[a] = s; s += cnt[a]; }
            g_offsets[NAG] = s;
        }
        __syncthreads();
        for (int i = t; i < BATCH; i += 256) {
            const int a = which[i];
            g_bucket[atomicAdd(&run[a], 1)] = i;
        }
        return;
    }
    /* convert: 16 rows per block (8 warps x 2 rows, half-warp per row) */
    const int warp = t >> 5, lane = t & 31;
    const int row = (blockIdx.x - 1) * 16 + warp * 2 + (lane >> 4);
    if (row >= BATCH) return;
    const int p = lane & 15;                 /* k-pair within chunk */
    const float2* xr = (const float2*)(x + (size_t)row * INF) + p;
    const int q = p >> 2, w = p & 3;
    #pragma unroll
    for (int c = 0; c < NCH; c++) {
        const float2 v = xr[c * 16];
        uint32_t h, l;
        split2(v.x, v.y, h, l);
        uint32_t* dst = g_xs[c][row];
        dst[q * 8 + w]     = h;
        dst[q * 8 + 4 + w] = l;
    }
}

/* ---------------- kernel 2: split-bf16 mma.sync GEMM ---------------- */
__global__ __launch_bounds__(128) void agent_mma_kernel(
    const float* __restrict__ x, const float* __restrict__ w,
    const float* __restrict__ bias, float* __restrict__ out)
{
    extern __shared__ char sm[];
    const uint32_t sb = smem_u32(sm);
    const int a     = blockIdx.y;
    const int mbase = blockIdx.x * MT;
    const int off   = g_offsets[a];
    const int cnt   = g_offsets[a + 1] - off;

    const int t    = threadIdx.x;
    const int lane = t & 31;
    const int warp = t >> 5;
    const int qr   = lane >> 2;
    const int qc   = lane & 3;

    /* ldmatrix per-lane address bases */
    const int aRow = ((lane >> 3) & 1) * 8;
    const int aK16 = ((lane >> 4) & 1) * 16;
    const int bRow = ((lane >> 4) & 1) * 8;
    const int bK16 = ((lane >> 3) & 1) * 16;
    uint32_t awb[2], alb[2], bxb[2], blb[2];
    #pragma unroll
    for (int mi = 0; mi < 2; mi++) {
        const uint32_t ro = (uint32_t)(warp * 32 + mi * 16 + aRow + (lane & 7)) * WROW_B + aK16;
        awb[mi] = sb + ST_WHI + ro;
        alb[mi] = sb + ST_WLO + ro;
    }
    #pragma unroll
    for (int nb = 0; nb < 2; nb++) {
        const uint32_t ro = (uint32_t)(nb * 16 + bRow + (lane & 7)) * WROW_B + bK16;
        bxb[nb] = sb + ST_XHI + ro;
        blb[nb] = sb + ST_XLO + ro;
    }

    /* coalesced W load mapping: 4 rows per warp-pass, 8 passes per chunk */
    const int wlr = lane >> 3;
    const int wlc = lane & 7;
    const float* Wbase = w + (size_t)a * OUTF * INF
                       + (size_t)(mbase + warp * 32 + wlr) * INF + wlc * 4;
    const uint32_t wsrow = (uint32_t)(warp * 32 + wlr);

    /* X mapping: slot = t>>2 (0..31), q = t&3; dst smem offsets fixed */
    const int xslot = t >> 2, xq4 = t & 3;
    const uint32_t xdst = sb + (uint32_t)xslot * WROW_B + xq4 * 16;

    float4 wpre[8];

    for (int n0 = blockIdx.z * NT; n0 < cnt; n0 += 2 * NT) {
        const int cntc = min(NT, cnt - n0);
        int sg = off + n0 + xslot;
        if (sg > BATCH - 1) sg = BATCH - 1;
        const int xrowg = g_bucket[sg];

        float acc[2][4][4];
        #pragma unroll
        for (int mi = 0; mi < 2; mi++)
            #pragma unroll
            for (int ni = 0; ni < 4; ni++)
                #pragma unroll
                for (int r = 0; r < 4; r++) acc[mi][ni][r] = 0.f;

        /* issue W LDG (to regs) + X cp.async (to stage c&1) for chunk c */
        auto ldg = [&](int c) {
            const int k0 = c * TK;
            #pragma unroll
            for (int ro = 0; ro < 8; ro++)
                wpre[ro] = *(const float4*)(Wbase + (size_t)ro * 4 * INF + k0);
            const uint32_t so = (uint32_t)(c & 1) * ST_SIZE;
            const uint32_t* xsrc = &g_xs[c][xrowg][xq4 * 8];
            CP_ASYNC16(xdst + ST_XHI + so, xsrc);
            CP_ASYNC16(xdst + ST_XLO + so, xsrc + 4);
        };

        auto sts = [&](int s) {
            char* base = sm + s * ST_SIZE;
            char* dw = base + wsrow * WROW_B + wlc * 8;
            #pragma unroll
            for (int ro = 0; ro < 8; ro++) {
                uint32_t h0, l0, h1, l1;
                split2(wpre[ro].x, wpre[ro].y, h0, l0);
                split2(wpre[ro].z, wpre[ro].w, h1, l1);
                const uint32_t roff = (uint32_t)ro * 4 * WROW_B;
                *(uint2*)(dw + ST_WHI + roff) = make_uint2(h0, h1);
                *(uint2*)(dw + ST_WLO + roff) = make_uint2(l0, l1);
            }
        };

        auto compute = [&](int s) {
            const uint32_t so = (uint32_t)s * ST_SIZE;
            #pragma unroll
            for (int kk = 0; kk < 2; kk++) {
                const uint32_t ko = so + kk * 32;
                uint32_t ahi[2][4], alo[2][4];
                #pragma unroll
                for (int mi = 0; mi < 2; mi++) {
                    LDSM_X4(ahi[mi][0], ahi[mi][1], ahi[mi][2], ahi[mi][3], awb[mi] + ko);
                    LDSM_X4(alo[mi][0], alo[mi][1], alo[mi][2], alo[mi][3], alb[mi] + ko);
                }
                #pragma unroll
                for (int nb = 0; nb < 2; nb++) {
                    uint32_t bh4[4], bl4[4];
                    LDSM_X4(bh4[0], bh4[1], bh4[2], bh4[3], bxb[nb] + ko);
                    LDSM_X4(bl4[0], bl4[1], bl4[2], bl4[3], blb[nb] + ko);
                    #pragma unroll
                    for (int half = 0; half < 2; half++) {
                        const int ni = nb * 2 + half;
                        uint32_t bh[2] = {bh4[2 * half], bh4[2 * half + 1]};
                        uint32_t bl[2] = {bl4[2 * half], bl4[2 * half + 1]};
                        #pragma unroll
                        for (int mi = 0; mi < 2; mi++) {
                            mma_bf16(acc[mi][ni], ahi[mi], bh);
                            mma_bf16(acc[mi][ni], alo[mi], bh);
                            mma_bf16(acc[mi][ni], ahi[mi], bl);
                        }
                    }
                }
            }
        };

        ldg(0);          /* W regs + X cp.async stage 0 */
        sts(0);          /* W stage 0 */
        for (int c = 0; c < NCH; c++) {
            CP_WAIT_ALL();          /* X for stage c&1 has landed */
            __syncthreads();
            if (c + 1 < NCH) ldg(c + 1);   /* W regs + X cp.async stage (c+1)&1 */
            compute(c & 1);
            if (c + 1 < NCH) sts((c + 1) & 1);
        }

        /* epilogue */
        #pragma unroll
        for (int mi = 0; mi < 2; mi++) {
            const int mg = mbase + warp * 32 + mi * 16 + qr;
            const float b0 = bias[a * OUTF + mg];
            const float b8 = bias[a * OUTF + mg + 8];
            #pragma unroll
            for (int ni = 0; ni < 4; ni++) {
                const int n = ni * 8 + qc * 2;
                if (n < cntc) {
                    const int r = g_bucket[off + n0 + n];
                    out[(size_t)r * OUTF + mg]     = acc[mi][ni][0] + b0;
                    out[(size_t)r * OUTF + mg + 8] = acc[mi][ni][2] + b8;
                }
                if (n + 1 < cntc) {
                    const int r = g_bucket[off + n0 + n + 1];
                    out[(size_t)r * OUTF + mg]     = acc[mi][ni][1] + b0;
                    out[(size_t)r * OUTF + mg + 8] = acc[mi][ni][3] + b8;
                }
            }
        }
        __syncthreads();
    }
}

extern "C" void kernel_launch(void* const* d_in, const int* in_sizes, int n_in,
                              void* d_out, int out_size) {
    const int*   which = (const int*)d_in[0];
    const float* x     = (const float*)d_in[1];
    const float* w     = (const float*)d_in[2];
    const float* b     = (const float*)d_in[3];
    float* out = (float*)d_out;

    cudaFuncSetAttribute(agent_mma_kernel,
                         cudaFuncAttributeMaxDynamicSharedMemorySize, SM_TOT);

    prep_kernel<<<1 + (BATCH + 15) / 16, 256>>>(which, x);
    agent_mma_kernel<<<dim3(OUTF / MT, NAG, 2), 128, SM_TOT>>>(x, w, b, out);
}